// round 7
// baseline (speedup 1.0000x reference)
#include <cuda_runtime.h>
#include <cuda_bf16.h>

#define BB 4
#define NN 10000
#define MM 10000
#define PP 128
#define KS 32
#define ZF 128

// ---------------- device scratch (static: no allocation) ----------------
__device__ float4 g_noisy4[BB * NN];      // (x,y,z, x^2+y^2+z^2)
__device__ float4 g_clean4[BB * MM];
__device__ float4 g_forigin[BB * PP];
__device__ float  g_zpart[BB * PP * ZF];  // Ws1[3:]^T z + bs1 per (b,p)
__device__ float4 g_fpts[BB * PP * KS];   // gathered noisy neighbors
__device__ float  g_estim[BB * PP * KS * 3];
__device__ float  g_partial[BB * PP];

__device__ __forceinline__ float finf() { return __int_as_float(0x7f800000); }

// packed f32x2 helpers (Blackwell FFMA2)
__device__ __forceinline__ unsigned long long fma2(unsigned long long a,
                                                   unsigned long long b,
                                                   unsigned long long c) {
    unsigned long long d;
    asm("fma.rn.f32x2 %0, %1, %2, %3;" : "=l"(d) : "l"(a), "l"(b), "l"(c));
    return d;
}
__device__ __forceinline__ unsigned long long pk2(float lo, float hi) {
    unsigned long long r;
    asm("mov.b64 %0, {%1, %2};" : "=l"(r) : "f"(lo), "f"(hi));
    return r;
}
__device__ __forceinline__ void upk2(float& lo, float& hi, unsigned long long v) {
    asm("mov.b64 {%0, %1}, %2;" : "=f"(lo), "=f"(hi) : "l"(v));
}

// ---------------- K0: pack point clouds as float4 with |r|^2 ----------------
__global__ void k0_pack(const float* __restrict__ noisy, const float* __restrict__ clean) {
    int i = blockIdx.x * blockDim.x + threadIdx.x;
    if (i < BB * NN) {
        float x = noisy[i * 3 + 0], y = noisy[i * 3 + 1], z = noisy[i * 3 + 2];
        g_noisy4[i] = make_float4(x, y, z, fmaf(x, x, fmaf(y, y, z * z)));
    }
    if (i < BB * MM) {
        float x = clean[i * 3 + 0], y = clean[i * 3 + 1], z = clean[i * 3 + 2];
        g_clean4[i] = make_float4(x, y, z, fmaf(x, x, fmaf(y, y, z * z)));
    }
}

// ---------------- K1: f_origin, feat(sampled), zpart ----------------
__global__ void k1_feat(const float* __restrict__ noisy, const int* __restrict__ sidx,
                        const float* __restrict__ Wf1, const float* __restrict__ bf1,
                        const float* __restrict__ Wf2, const float* __restrict__ bf2,
                        const float* __restrict__ Ws1, const float* __restrict__ bs1) {
    int bp = blockIdx.x;            // 0..511
    int b = bp >> 7, p = bp & 127;
    int tid = threadIdx.x;          // 128 threads
    __shared__ float xyz[3];
    __shared__ float h[64];
    __shared__ float z[128];

    if (tid == 0) {
        int si = sidx[p];
        const float* s = noisy + ((size_t)b * NN + si) * 3;
        xyz[0] = s[0]; xyz[1] = s[1]; xyz[2] = s[2];
        g_forigin[bp] = make_float4(s[0], s[1], s[2], 0.f);
    }
    __syncthreads();

    if (tid < 64) {
        float a = bf1[tid];
        a = fmaf(xyz[0], Wf1[0 * 64 + tid], a);
        a = fmaf(xyz[1], Wf1[1 * 64 + tid], a);
        a = fmaf(xyz[2], Wf1[2 * 64 + tid], a);
        h[tid] = fmaxf(a, 0.f);
    }
    __syncthreads();

    {
        float a = bf2[tid];
#pragma unroll 16
        for (int i = 0; i < 64; ++i) a = fmaf(h[i], Wf2[i * 128 + tid], a);
        z[tid] = a;                 // feat: no relu on second layer
    }
    __syncthreads();

    {
        float a = bs1[tid];
#pragma unroll 16
        for (int i = 0; i < 128; ++i) a = fmaf(z[i], Ws1[(3 + i) * 128 + tid], a);
        g_zpart[bp * ZF + tid] = a;
    }
}

// ---------------- K2: KNN1 top-32 via 4-level radix select ----------------
__global__ __launch_bounds__(256) void k2_knn1() {
    int bp = blockIdx.x;            // one query per block
    int b = bp >> 7;
    int tid = threadIdx.x, lane = tid & 31;
    __shared__ unsigned keys[NN];   // 40 KB
    __shared__ unsigned hist[257];  // 256 bins + 1 dummy
    __shared__ unsigned s_prefix, s_want, s_cnt;

    float4 q = g_forigin[bp];
    float m2x = -2.0f * q.x, m2y = -2.0f * q.y, m2z = -2.0f * q.z;
    for (int r = tid; r < NN; r += 256) {
        float4 v = g_noisy4[b * NN + r];
        float s = fmaf(v.x, m2x, fmaf(v.y, m2y, fmaf(v.z, m2z, v.w))); // d2 - |q|^2
        unsigned u = __float_as_uint(s);
        u ^= ((unsigned)((int)u >> 31)) | 0x80000000u;  // monotone float->uint
        keys[r] = u;
    }

    unsigned prefix = 0u, want = 32u;
#pragma unroll
    for (int level = 0; level < 4; ++level) {
        const int shift = 24 - 8 * level;
        const unsigned mask = (level == 0) ? 0u : (0xFFFFFFFFu << (shift + 8));
        hist[tid] = 0u;
        if (tid == 0) hist[256] = 0u;
        __syncthreads();             // keys + hist visible
        for (int r = tid; r < NN; r += 256) {
            unsigned k = keys[r];
            bool match = ((k ^ prefix) & mask) == 0u;
            unsigned bin = (k >> shift) & 0xFFu;
            atomicAdd(&hist[match ? bin : 256u], 1u);   // branchless (dummy bin)
        }
        __syncthreads();
        if (tid < 32) {
            unsigned c[8], lsum = 0u;
#pragma unroll
            for (int j = 0; j < 8; ++j) { c[j] = hist[8 * lane + j]; lsum += c[j]; }
            unsigned incl = lsum;
#pragma unroll
            for (int off = 1; off < 32; off <<= 1) {
                unsigned t = __shfl_up_sync(0xFFFFFFFFu, incl, off);
                if (lane >= off) incl += t;
            }
            unsigned excl = incl - lsum;
            if (excl < want && want <= incl) {          // exactly one lane
                unsigned acc = excl;
#pragma unroll
                for (int j = 0; j < 8; ++j) {
                    if (want <= acc + c[j]) {
                        s_prefix = prefix | ((unsigned)(8 * lane + j) << shift);
                        s_want = want - acc;
                        break;
                    }
                    acc += c[j];
                }
            }
        }
        __syncthreads();
        prefix = s_prefix; want = s_want;
        __syncthreads();            // protect s_prefix before next level reuse
    }
    unsigned T = prefix;            // exact 32nd-smallest key

    if (tid == 0) s_cnt = 0u;
    __syncthreads();
    for (int r = tid; r < NN; r += 256) {
        if (keys[r] <= T) {
            unsigned pos = atomicAdd(&s_cnt, 1u);
            if (pos < 32u) g_fpts[bp * KS + pos] = g_noisy4[b * NN + r];
        }
    }
}

// ---------------- K3: score MLP — ONE WARP PER 4 ROWS ----------------
__global__ __launch_bounds__(256) void k3_mlp(const float* __restrict__ Ws1,
                                              const float* __restrict__ Ws2,
                                              const float* __restrict__ bs2,
                                              const float* __restrict__ Ws3,
                                              const float* __restrict__ bs3) {
    __shared__ float hsh[8][4][128];
    int w = threadIdx.x >> 5, lane = threadIdx.x & 31;
    int rbase = (blockIdx.x * 8 + w) * 4;   // rows rbase..rbase+3 share bp
    int bp = rbase >> 5;

    float4 o = g_forigin[bp];
    float X0[4], X1[4], X2[4];
#pragma unroll
    for (int j = 0; j < 4; ++j) {
        float4 f = g_fpts[rbase + j];       // warp-uniform address -> L1 broadcast
        X0[j] = f.x - o.x; X1[j] = f.y - o.y; X2[j] = f.z - o.z;
    }

    float4 zp = *(const float4*)(g_zpart + bp * ZF + lane * 4);
    float4 w0 = *(const float4*)(Ws1 + 0 * 128 + lane * 4);
    float4 w1 = *(const float4*)(Ws1 + 1 * 128 + lane * 4);
    float4 w2 = *(const float4*)(Ws1 + 2 * 128 + lane * 4);
#pragma unroll
    for (int j = 0; j < 4; ++j) {
        float4 h4;
        h4.x = fmaxf(fmaf(X2[j], w2.x, fmaf(X1[j], w1.x, fmaf(X0[j], w0.x, zp.x))), 0.f);
        h4.y = fmaxf(fmaf(X2[j], w2.y, fmaf(X1[j], w1.y, fmaf(X0[j], w0.y, zp.y))), 0.f);
        h4.z = fmaxf(fmaf(X2[j], w2.z, fmaf(X1[j], w1.z, fmaf(X0[j], w0.z, zp.z))), 0.f);
        h4.w = fmaxf(fmaf(X2[j], w2.w, fmaf(X1[j], w1.w, fmaf(X0[j], w0.w, zp.w))), 0.f);
        *(float4*)&hsh[w][j][lane * 4] = h4;
    }
    __syncwarp();

    float b20 = bs2[2 * lane], b21 = bs2[2 * lane + 1];
    float a0[4], a1[4];
#pragma unroll
    for (int j = 0; j < 4; ++j) { a0[j] = b20; a1[j] = b21; }
    const float2* __restrict__ W2 = (const float2*)(Ws2) + lane;  // (i, 2*lane)
#pragma unroll 8
    for (int i = 0; i < 128; i += 4) {
        float2 wv0 = W2[(i + 0) * 32];
        float2 wv1 = W2[(i + 1) * 32];
        float2 wv2 = W2[(i + 2) * 32];
        float2 wv3 = W2[(i + 3) * 32];
#pragma unroll
        for (int j = 0; j < 4; ++j) {
            float4 hv = *(const float4*)&hsh[w][j][i];   // broadcast LDS.128
            a0[j] = fmaf(hv.x, wv0.x, a0[j]); a1[j] = fmaf(hv.x, wv0.y, a1[j]);
            a0[j] = fmaf(hv.y, wv1.x, a0[j]); a1[j] = fmaf(hv.y, wv1.y, a1[j]);
            a0[j] = fmaf(hv.z, wv2.x, a0[j]); a1[j] = fmaf(hv.z, wv2.y, a1[j]);
            a0[j] = fmaf(hv.w, wv3.x, a0[j]); a1[j] = fmaf(hv.w, wv3.y, a1[j]);
        }
    }

    const float* __restrict__ w3 = Ws3 + 6 * lane;
    float w30 = w3[0], w31 = w3[1], w32 = w3[2];
    float w33 = w3[3], w34 = w3[4], w35 = w3[5];
    float ob0 = bs3[0], ob1 = bs3[1], ob2 = bs3[2];
#pragma unroll
    for (int j = 0; j < 4; ++j) {
        float h20 = fmaxf(a0[j], 0.f), h21 = fmaxf(a1[j], 0.f);
        float p0 = fmaf(h20, w30, h21 * w33);
        float p1 = fmaf(h20, w31, h21 * w34);
        float p2 = fmaf(h20, w32, h21 * w35);
#pragma unroll
        for (int off = 16; off > 0; off >>= 1) {
            p0 += __shfl_xor_sync(0xFFFFFFFFu, p0, off);
            p1 += __shfl_xor_sync(0xFFFFFFFFu, p1, off);
            p2 += __shfl_xor_sync(0xFFFFFFFFu, p2, off);
        }
        if (lane == 0) {
            g_estim[(rbase + j) * 3 + 0] = p0 + ob0;
            g_estim[(rbase + j) * 3 + 1] = p1 + ob1;
            g_estim[(rbase + j) * 3 + 2] = p2 + ob2;
        }
    }
}

// insertion into sorted 4-element top list
#define INS4(s, id, s0, s1, s2, s3, i0, i1, i2, i3)             \
    if ((s) < (s3)) {                                           \
        if ((s) < (s2)) {                                       \
            (s3) = (s2); (i3) = (i2);                           \
            if ((s) < (s1)) {                                   \
                (s2) = (s1); (i2) = (i1);                       \
                if ((s) < (s0)) { (s1) = (s0); (i1) = (i0); (s0) = (s); (i0) = (id); } \
                else { (s1) = (s); (i1) = (id); }               \
            } else { (s2) = (s); (i2) = (id); }                 \
        } else { (s3) = (s); (i3) = (id); }                     \
    }

// ---------------- K4: KNN2 top-4, SoA tile + packed f32x2 distance ----------
__global__ __launch_bounds__(256) void k4_knn2() {
    int bp = blockIdx.x;
    int b = bp >> 7;
    int tid = threadIdx.x, lane = tid & 31, w = tid >> 5;   // 8 warps

    __shared__ __align__(16) float sx[2048];     // SoA tile: 32 KB total
    __shared__ __align__(16) float sy[2048];
    __shared__ __align__(16) float sz[2048];
    __shared__ __align__(16) float sw[2048];
    __shared__ float cs[8][32][4];
    __shared__ int   ci[8][32][4];

    float4 f = g_fpts[bp * KS + lane];           // lane = query k
    unsigned long long M2X = pk2(-2.0f * f.x, -2.0f * f.x);
    unsigned long long M2Y = pk2(-2.0f * f.y, -2.0f * f.y);
    unsigned long long M2Z = pk2(-2.0f * f.z, -2.0f * f.z);
    float m2x = -2.0f * f.x, m2y = -2.0f * f.y, m2z = -2.0f * f.z;

    float s0 = finf(), s1 = finf(), s2 = finf(), s3 = finf();
    int   i0 = 0, i1 = 0, i2 = 0, i3 = 0;

    for (int t0 = 0; t0 < MM; t0 += 2048) {
        int n = min(2048, MM - t0);
        __syncthreads();
        for (int j = tid; j < n; j += 256) {
            float4 v = g_clean4[b * MM + t0 + j];
            sx[j] = v.x; sy[j] = v.y; sz[j] = v.z; sw[j] = v.w;
        }
        __syncthreads();
        int chunk = (((n + 7) >> 3) + 3) & ~3;   // per-warp, multiple of 4
        int start = w * chunk;
        int end = min(start + chunk, n);
        int r = start;
#pragma unroll 2
        for (; r + 4 <= end; r += 4) {
            int q = r >> 2;
            ulonglong2 xv = ((const ulonglong2*)sx)[q];   // broadcast LDS.128
            ulonglong2 yv = ((const ulonglong2*)sy)[q];
            ulonglong2 zv = ((const ulonglong2*)sz)[q];
            ulonglong2 wv = ((const ulonglong2*)sw)[q];
            unsigned long long p01 = fma2(xv.x, M2X, fma2(yv.x, M2Y, fma2(zv.x, M2Z, wv.x)));
            unsigned long long p23 = fma2(xv.y, M2X, fma2(yv.y, M2Y, fma2(zv.y, M2Z, wv.y)));
            float sa, sb, sc, sd;
            upk2(sa, sb, p01);
            upk2(sc, sd, p23);
            float m = fminf(fminf(sa, sb), fminf(sc, sd));
            if (m < s3) {                        // rare: ~30x per 10000
                INS4(sa, t0 + r + 0, s0, s1, s2, s3, i0, i1, i2, i3);
                INS4(sb, t0 + r + 1, s0, s1, s2, s3, i0, i1, i2, i3);
                INS4(sc, t0 + r + 2, s0, s1, s2, s3, i0, i1, i2, i3);
                INS4(sd, t0 + r + 3, s0, s1, s2, s3, i0, i1, i2, i3);
            }
        }
        for (; r < end; ++r) {
            float s = fmaf(sx[r], m2x, fmaf(sy[r], m2y, fmaf(sz[r], m2z, sw[r])));
            int id = t0 + r;
            INS4(s, id, s0, s1, s2, s3, i0, i1, i2, i3);
        }
    }
    __syncthreads();
    cs[w][lane][0] = s0; cs[w][lane][1] = s1; cs[w][lane][2] = s2; cs[w][lane][3] = s3;
    ci[w][lane][0] = i0; ci[w][lane][1] = i1; ci[w][lane][2] = i2; ci[w][lane][3] = i3;
    __syncthreads();

    if (w == 0) {
        float b0 = finf(), b1 = finf(), b2 = finf(), b3 = finf();
        int   j0 = 0, j1 = 0, j2 = 0, j3 = 0;
#pragma unroll
        for (int ww = 0; ww < 8; ++ww)
#pragma unroll
            for (int jj = 0; jj < 4; ++jj) {
                float s = cs[ww][lane][jj];
                int id = ci[ww][lane][jj];
                INS4(s, id, b0, b1, b2, b3, j0, j1, j2, j3);
            }
        float4 c0 = g_clean4[b * MM + j0];
        float4 c1 = g_clean4[b * MM + j1];
        float4 c2 = g_clean4[b * MM + j2];
        float4 c3 = g_clean4[b * MM + j3];
        float gx = (c0.x + c1.x + c2.x + c3.x) * 0.25f - f.x;
        float gy = (c0.y + c1.y + c2.y + c3.y) * 0.25f - f.y;
        float gz = (c0.z + c1.z + c2.z + c3.z) * 0.25f - f.z;
        const float* e = g_estim + (bp * KS + lane) * 3;
        float d0 = e[0] - gx, d1 = e[1] - gy, d2v = e[2] - gz;
        float err = fmaf(d0, d0, fmaf(d1, d1, d2v * d2v));
#pragma unroll
        for (int off = 16; off > 0; off >>= 1)
            err += __shfl_xor_sync(0xFFFFFFFFu, err, off);
        if (lane == 0) g_partial[bp] = err;
    }
}

// ---------------- K5: deterministic final reduce ----------------
__global__ void k5_reduce(float* __restrict__ out) {
    __shared__ float sm[512];
    int tid = threadIdx.x;
    sm[tid] = g_partial[tid];
    __syncthreads();
#pragma unroll
    for (int s = 256; s > 0; s >>= 1) {
        if (tid < s) sm[tid] += sm[tid + s];
        __syncthreads();
    }
    // loss = 0.5 * mean_{B*P*K}( sum_d (.)^2 / SIGMA ) = total * 0.5*100/16384
    if (tid == 0) out[0] = sm[0] * (50.0f / 16384.0f);
}

extern "C" void kernel_launch(void* const* d_in, const int* in_sizes, int n_in,
                              void* d_out, int out_size) {
    const float* noisy = (const float*)d_in[0];
    const float* clean = (const float*)d_in[1];
    const int*   sidx  = (const int*)d_in[2];
    const float* Wf1 = (const float*)d_in[3];
    const float* bf1 = (const float*)d_in[4];
    const float* Wf2 = (const float*)d_in[5];
    const float* bf2 = (const float*)d_in[6];
    const float* Ws1 = (const float*)d_in[7];
    const float* bs1 = (const float*)d_in[8];
    const float* Ws2 = (const float*)d_in[9];
    const float* bs2 = (const float*)d_in[10];
    const float* Ws3 = (const float*)d_in[11];
    const float* bs3 = (const float*)d_in[12];
    float* out = (float*)d_out;

    k0_pack<<<(BB * NN + 255) / 256, 256>>>(noisy, clean);
    k1_feat<<<BB * PP, 128>>>(noisy, sidx, Wf1, bf1, Wf2, bf2, Ws1, bs1);
    k2_knn1<<<BB * PP, 256>>>();
    k3_mlp<<<BB * PP * KS / 32, 256>>>(Ws1, Ws2, bs2, Ws3, bs3);
    k4_knn2<<<BB * PP, 256>>>();
    k5_reduce<<<1, 512>>>(out);
}